// round 13
// baseline (speedup 1.0000x reference)
#include <cuda_runtime.h>
#include <cuda_fp16.h>
#include <cuda_bf16.h>

#define NN   50000
#define EE   1600000
#define DIN  128
#define DOUT 256
#define DA   32
#define NBLK ((NN + 1023) / 1024)   // 49

typedef unsigned long long ull;

// ---------------- device scratch (static, no allocations) ----------------
__device__ __half2 g_arowh[NN * 16];        // a_row as half2 (3.2 MB)
__device__ __half2 g_acolh[NN * 16];        // a_col as half2 (3.2 MB)
__device__ __half2 g_xh[NN * 64];           // x as half2     (12.8 MB)
__device__ __half2 g_hh[NN * 64];           // h as half2     (12.8 MB)
__device__ __half  g_Wh[DIN * DOUT];        // W_x as half    (64 KB)
__device__ float  g_deg[NN];                // zero-init; self-cleaned by spmm
__device__ int    g_cnt [NN];               // zero-init; self-cleaned by scanA
__device__ int    g_cnt2[NN];               // zero-init; self-cleaned by spmm
__device__ int    g_off [NN + 1];
__device__ int    g_bsum[NBLK];
__device__ float  g_eaf[EE];                // exp(atten), EDGE order — 6.4 MB
__device__ uint2  g_ecol[EE];               // {col*32, final val bits} CSR order — 12.8 MB

// ---------------- kernel 1: projections + x->half2 convert ----------------
#define PROJ_NODES 16
__global__ __launch_bounds__(256) void proj_kernel(
    const float* __restrict__ x,
    const float* __restrict__ Wr,
    const float* __restrict__ Wc)
{
    __shared__ float Wsh[DIN][2 * DA];          // cols [0,32)=W_row, [32,64)=W_col
    __shared__ float xsh[PROJ_NODES][DIN + 1];
    int t = threadIdx.x;

    for (int i = t; i < DIN * DA; i += 256) {
        int k = i >> 5, j = i & 31;
        Wsh[k][j]      = Wr[i];
        Wsh[k][j + 32] = Wc[i];
    }
    int node0 = blockIdx.x * PROJ_NODES;
    for (int i = t; i < PROJ_NODES * DIN; i += 256) {
        int n = i >> 7, k = i & 127;
        int gn = node0 + n;
        xsh[n][k] = (gn < NN) ? x[gn * DIN + k] : 0.f;
    }
    __syncthreads();

    // write x as half2 (free conversion: x already staged in smem)
    for (int i = t; i < PROJ_NODES * 64; i += 256) {
        int n = i >> 6, k2 = i & 63;
        int gn = node0 + n;
        if (gn < NN)
            g_xh[gn * 64 + k2] = __floats2half2_rn(xsh[n][2 * k2], xsh[n][2 * k2 + 1]);
    }

    int n  = t & 15;       // local node
    int g  = t >> 4;       // output group 0..15 -> dims g*4..g*4+3
    int j0 = g * 4;
    float a0 = 0.f, a1 = 0.f, a2 = 0.f, a3 = 0.f;
#pragma unroll 8
    for (int k = 0; k < DIN; k++) {
        float xv = xsh[n][k];
        a0 += xv * Wsh[k][j0 + 0];
        a1 += xv * Wsh[k][j0 + 1];
        a2 += xv * Wsh[k][j0 + 2];
        a3 += xv * Wsh[k][j0 + 3];
    }
    int gn = node0 + n;
    if (gn < NN) {
        if (j0 < DA) {
            g_arowh[gn * 16 + (j0 >> 1)]     = __floats2half2_rn(a0, a1);
            g_arowh[gn * 16 + (j0 >> 1) + 1] = __floats2half2_rn(a2, a3);
        } else {
            int j = j0 - DA;
            g_acolh[gn * 16 + (j >> 1)]      = __floats2half2_rn(a0, a1);
            g_acolh[gn * 16 + (j >> 1) + 1]  = __floats2half2_rn(a2, a3);
        }
    }
}

// ---------------- kernel 1b (stream 1): per-edge attention in EDGE order ----------------
// overlapped with the hist/scan chain; writes ea + accumulates denominator.
__device__ __forceinline__ float att_dot(const uint4* ar4, const uint4* ac4) {
    float dot = 0.f;
#pragma unroll
    for (int q = 0; q < 4; q++) {
        uint4 A = __ldg(&ar4[q]), B = __ldg(&ac4[q]);
        const __half2* ah = (const __half2*)&A;
        const __half2* bh = (const __half2*)&B;
#pragma unroll
        for (int j = 0; j < 4; j++) {
            float2 a = __half22float2(ah[j]);
            float2 b = __half22float2(bh[j]);
            dot += a.x * b.x + a.y * b.y;
        }
    }
    return dot;
}

__global__ __launch_bounds__(256) void edge_atten_kernel(
    const int* __restrict__ row,
    const int* __restrict__ col)
{
    int i = blockIdx.x * blockDim.x + threadIdx.x;
    int e = i * 2;
    if (e >= EE) return;
    int2 r2 = *(const int2*)&row[e];
    int2 c2 = *(const int2*)&col[e];

    float d0 = att_dot((const uint4*)&g_arowh[r2.x * 16], (const uint4*)&g_acolh[c2.x * 16]);
    float d1 = att_dot((const uint4*)&g_arowh[r2.y * 16], (const uint4*)&g_acolh[c2.y * 16]);

    float s0 = d0 * 0.17677669529663687f;      // rsqrt(32)
    float s1 = d1 * 0.17677669529663687f;
    if (s0 < 0.f) s0 *= 0.2f;                  // leaky relu
    if (s1 < 0.f) s1 *= 0.2f;
    float ea0 = __expf(s0);
    float ea1 = __expf(s1);
    *(float2*)&g_eaf[e] = make_float2(ea0, ea1);
    atomicAdd(&g_deg[r2.x], ea0);
    atomicAdd(&g_deg[r2.y], ea1);
}

// ---------------- kernel 2: degree histogram (4 edges/thread) + W convert ----------------
__global__ void hist_kernel(const int* __restrict__ row, const float* __restrict__ W) {
    int i = blockIdx.x * blockDim.x + threadIdx.x;
    if (i < DIN * DOUT) g_Wh[i] = __float2half(W[i]);
    int e4 = i * 4;
    if (e4 < EE) {
        int4 r = *(const int4*)&row[e4];
        atomicAdd(&g_cnt[r.x], 1);
        atomicAdd(&g_cnt[r.y], 1);
        atomicAdd(&g_cnt[r.z], 1);
        atomicAdd(&g_cnt[r.w], 1);
    }
}

// ---------------- kernel 3a: block scan (self-cleans g_cnt for next replay) ----------------
__global__ __launch_bounds__(1024) void scanA_kernel() {
    __shared__ int wsum[32];
    int b = blockIdx.x, t = threadIdx.x;
    int i = b * 1024 + t;
    int lane = t & 31, w = t >> 5;
    int v = (i < NN) ? g_cnt[i] : 0;
    if (i < NN) g_cnt[i] = 0;                 // self-clean for next graph replay
    int s = v;
#pragma unroll
    for (int d = 1; d < 32; d <<= 1) {
        int n = __shfl_up_sync(0xffffffffu, s, d);
        if (lane >= d) s += n;
    }
    if (lane == 31) wsum[w] = s;
    __syncthreads();
    if (w == 0) {
        int ws = wsum[lane];
#pragma unroll
        for (int d = 1; d < 32; d <<= 1) {
            int n = __shfl_up_sync(0xffffffffu, ws, d);
            if (lane >= d) ws += n;
        }
        wsum[lane] = ws;
    }
    __syncthreads();
    int incl = s + (w > 0 ? wsum[w - 1] : 0);
    if (i < NN) g_off[i + 1] = incl;          // block-local inclusive
    if (t == 1023) g_bsum[b] = incl;          // block total
}

// ---------------- kernel 3b: merged block-sum scan + offset add ----------------
__global__ __launch_bounds__(1024) void scanBC_kernel() {
    __shared__ int pre[64];
    int b = blockIdx.x, t = threadIdx.x;
    if (t < 64) pre[t] = (t < NBLK) ? g_bsum[t] : 0;
    __syncthreads();
#pragma unroll
    for (int s = 1; s < 64; s <<= 1) {
        int a = (t >= s && t < 64) ? pre[t - s] : 0;
        __syncthreads();
        if (t < 64) pre[t] += a;
        __syncthreads();
    }
    int add = (b > 0) ? pre[b - 1] : 0;
    int i = b * 1024 + t;
    if (i < NN) g_off[i + 1] += add;
    if (b == 0 && t == 0) g_off[0] = 0;
}

// ---------------- kernel 4: CSR scatter of final edge weight (4 edges/thread) ----------------
// val = 0.5*(adj + ea/deg) computed here — fused kernel becomes pure SpMM.
__global__ __launch_bounds__(256) void scatter_kernel(
    const int*   __restrict__ row,
    const int*   __restrict__ col,
    const float* __restrict__ adj)
{
    int i = blockIdx.x * blockDim.x + threadIdx.x;
    int e = i * 4;
    if (e >= EE) return;
    int4   r4 = *(const int4*)&row[e];
    int4   c4 = *(const int4*)&col[e];
    float4 a4 = *(const float4*)&adj[e];
    float4 e4 = *(const float4*)&g_eaf[e];

    float v0 = 0.5f * (a4.x + e4.x / (g_deg[r4.x] + 1e-15f));
    float v1 = 0.5f * (a4.y + e4.y / (g_deg[r4.y] + 1e-15f));
    float v2 = 0.5f * (a4.z + e4.z / (g_deg[r4.z] + 1e-15f));
    float v3 = 0.5f * (a4.w + e4.w / (g_deg[r4.w] + 1e-15f));

    int p0 = g_off[r4.x] + atomicAdd(&g_cnt2[r4.x], 1);
    g_ecol[p0] = make_uint2((unsigned)(c4.x * 32), __float_as_uint(v0));
    int p1 = g_off[r4.y] + atomicAdd(&g_cnt2[r4.y], 1);
    g_ecol[p1] = make_uint2((unsigned)(c4.y * 32), __float_as_uint(v1));
    int p2 = g_off[r4.z] + atomicAdd(&g_cnt2[r4.z], 1);
    g_ecol[p2] = make_uint2((unsigned)(c4.z * 32), __float_as_uint(v2));
    int p3 = g_off[r4.w] + atomicAdd(&g_cnt2[r4.w], 1);
    g_ecol[p3] = make_uint2((unsigned)(c4.w * 32), __float_as_uint(v3));
}

// ---------------- kernel 5: pure SpMM, warp per node (single pass) ----------------
__global__ __launch_bounds__(256) void spmm_kernel() {
    int w = threadIdx.x >> 5, lane = threadIdx.x & 31;
    int i = blockIdx.x * 8 + w;
    if (i >= NN) return;
    int start = g_off[i], end = g_off[i + 1];
    if (lane == 0) { g_cnt2[i] = 0; g_deg[i] = 0.f; }   // self-clean for next replay

    __shared__ float2 stage[8][32];            // per-warp broadcast buffer

    const uint2* x2 = (const uint2*)g_xh;      // one uint2 = 4 dims; row = 32 uint2
    float a0 = 0.f, a1 = 0.f, a2 = 0.f, a3 = 0.f;
    int base = start;
    for (; base + 32 <= end; base += 32) {
        uint2 ca = g_ecol[base + lane];        // {col*32, val bits}
        stage[w][lane] = make_float2(__uint_as_float(ca.y), __uint_as_float(ca.x));
        __syncwarp();
#pragma unroll 8
        for (int j = 0; j < 32; j++) {
            float2 vc = stage[w][j];                       // LDS.64 broadcast
            float v  = vc.x;
            int   cb = (int)__float_as_uint(vc.y);
            uint2 xv = __ldg(&x2[cb + lane]);
            __half2 xa = *reinterpret_cast<__half2*>(&xv.x);
            __half2 xb = *reinterpret_cast<__half2*>(&xv.y);
            float2 fa = __half22float2(xa);
            float2 fb = __half22float2(xb);
            a0 += v * fa.x; a1 += v * fa.y;
            a2 += v * fb.x; a3 += v * fb.y;
        }
        __syncwarp();
    }
    if (base < end) {
        int k = base + lane;
        float myval = 0.f;
        unsigned mycol = 0;
        if (k < end) {
            uint2 ca = g_ecol[k];
            myval = __uint_as_float(ca.y);
            mycol = ca.x;
        }
        stage[w][lane] = make_float2(myval, __uint_as_float(mycol));
        __syncwarp();
        int m = end - base;
        for (int j = 0; j < m; j++) {
            float2 vc = stage[w][j];
            float v  = vc.x;
            int   cb = (int)__float_as_uint(vc.y);
            uint2 xv = __ldg(&x2[cb + lane]);
            __half2 xa = *reinterpret_cast<__half2*>(&xv.x);
            __half2 xb = *reinterpret_cast<__half2*>(&xv.y);
            float2 fa = __half22float2(xa);
            float2 fb = __half22float2(xb);
            a0 += v * fa.x; a1 += v * fa.y;
            a2 += v * fb.x; a3 += v * fb.y;
        }
    }

    uint2 o;
    __half2 o0 = __floats2half2_rn(a0, a1);
    __half2 o1 = __floats2half2_rn(a2, a3);
    o.x = *reinterpret_cast<unsigned*>(&o0);
    o.y = *reinterpret_cast<unsigned*>(&o1);
    *(uint2*)&g_hh[i * 64 + lane * 2] = o;
}

// ---------------- kernel 6: out = h @ W_x + b_x (HMMA m16n8k16) ----------------
// BM=128, BN=128, single K=128 pass. 256 threads (8 warps), warp tile 32x64.
#define LDA 136
#define LDB 136
__global__ __launch_bounds__(256) void gemm_kernel(
    const float* __restrict__ bias,
    float* __restrict__ out)
{
    extern __shared__ __half sm[];
    __half* As = sm;                 // [128][LDA]
    __half* Bs = sm + 128 * LDA;     // [128][LDB]

    int tid = threadIdx.x;
    int m0  = blockIdx.y * 128;
    int n0g = blockIdx.x * 128;

    // load A: h rows m0..m0+127 (256 B each = 16 uint4)
    const uint4* hsrc = (const uint4*)g_hh;
#pragma unroll
    for (int p = 0; p < 8; p++) {
        int idx = tid + 256 * p;
        int r = idx >> 4, seg = idx & 15;
        uint4 v = make_uint4(0u, 0u, 0u, 0u);
        if (m0 + r < NN) v = hsrc[(m0 + r) * 16 + seg];
        *(uint4*)&As[r * LDA + seg * 8] = v;
    }
    // load B: W rows k=0..127, cols n0g..n0g+127 (16 uint4 per row slice)
    const uint4* wsrc = (const uint4*)g_Wh;
#pragma unroll
    for (int p = 0; p < 8; p++) {
        int idx = tid + 256 * p;
        int kk = idx >> 4, seg = idx & 15;
        uint4 v = wsrc[kk * 32 + (n0g >> 3) + seg];
        *(uint4*)&Bs[kk * LDB + seg * 8] = v;
    }
    __syncthreads();

    int w    = tid >> 5;
    int lane = tid & 31;
    int wm = (w & 3) * 32;       // warp row offset
    int wn = (w >> 2) * 64;      // warp col offset

    float acc[2][8][4];
#pragma unroll
    for (int mt = 0; mt < 2; mt++)
#pragma unroll
        for (int nt = 0; nt < 8; nt++)
#pragma unroll
            for (int q = 0; q < 4; q++) acc[mt][nt][q] = 0.f;

#pragma unroll
    for (int ks = 0; ks < 8; ks++) {
        int k0 = ks * 16;
        unsigned afr[2][4];
#pragma unroll
        for (int mt = 0; mt < 2; mt++) {
            int r = wm + mt * 16 + (lane & 15);
            int c = k0 + (lane >> 4) * 8;
            unsigned addr = (unsigned)__cvta_generic_to_shared(&As[r * LDA + c]);
            asm volatile("ldmatrix.sync.aligned.m8n8.x4.shared.b16 {%0,%1,%2,%3}, [%4];"
                : "=r"(afr[mt][0]), "=r"(afr[mt][1]), "=r"(afr[mt][2]), "=r"(afr[mt][3])
                : "r"(addr));
        }
        unsigned bfr[8][2];
#pragma unroll
        for (int ntp = 0; ntp < 4; ntp++) {
            int kk = k0 + (lane & 15);
            int nn = wn + ntp * 16 + (lane >> 4) * 8;
            unsigned addr = (unsigned)__cvta_generic_to_shared(&Bs[kk * LDB + nn]);
            unsigned r0, r1, r2, r3;
            asm volatile("ldmatrix.sync.aligned.m8n8.x4.trans.shared.b16 {%0,%1,%2,%3}, [%4];"
                : "=r"(r0), "=r"(r1), "=r"(r2), "=r"(r3) : "r"(addr));
            bfr[ntp * 2][0] = r0;     bfr[ntp * 2][1] = r1;
            bfr[ntp * 2 + 1][0] = r2; bfr[ntp * 2 + 1][1] = r3;
        }
#pragma unroll
        for (int mt = 0; mt < 2; mt++)
#pragma unroll
            for (int nt = 0; nt < 8; nt++) {
                asm volatile(
                    "mma.sync.aligned.m16n8k16.row.col.f32.f16.f16.f32 "
                    "{%0,%1,%2,%3}, {%4,%5,%6,%7}, {%8,%9}, {%0,%1,%2,%3};"
                    : "+f"(acc[mt][nt][0]), "+f"(acc[mt][nt][1]),
                      "+f"(acc[mt][nt][2]), "+f"(acc[mt][nt][3])
                    : "r"(afr[mt][0]), "r"(afr[mt][1]), "r"(afr[mt][2]), "r"(afr[mt][3]),
                      "r"(bfr[nt][0]), "r"(bfr[nt][1]));
            }
    }

    // epilogue
    int g   = lane >> 2;
    int tig = lane & 3;
#pragma unroll
    for (int mt = 0; mt < 2; mt++) {
#pragma unroll
        for (int nt = 0; nt < 8; nt++) {
            int colg = n0g + wn + nt * 8 + tig * 2;
            float b0 = bias[colg], b1 = bias[colg + 1];
            int r0 = m0 + wm + mt * 16 + g;
            if (r0 < NN) {
                float2 v0 = make_float2(acc[mt][nt][0] + b0, acc[mt][nt][1] + b1);
                *(float2*)&out[r0 * DOUT + colg] = v0;
            }
            int r1 = r0 + 8;
            if (r1 < NN) {
                float2 v1 = make_float2(acc[mt][nt][2] + b0, acc[mt][nt][3] + b1);
                *(float2*)&out[r1 * DOUT + colg] = v1;
            }
        }
    }
}

// ---------------- launch ----------------
extern "C" void kernel_launch(void* const* d_in, const int* in_sizes, int n_in,
                              void* d_out, int out_size)
{
    const float* x    = (const float*)d_in[0];
    const int*   row  = (const int*)  d_in[1];
    const int*   col  = (const int*)  d_in[2];
    const float* adj  = (const float*)d_in[3];
    const float* Wr   = (const float*)d_in[4];
    const float* Wc   = (const float*)d_in[5];
    const float* Wx   = (const float*)d_in[6];
    const float* bx   = (const float*)d_in[7];
    float* out = (float*)d_out;

    // one-time resources (no device memory; identical captured work every call)
    static cudaStream_t s1 = nullptr;
    static cudaEvent_t evFork = nullptr, evJoin = nullptr;
    static bool smem_set = false;
    const int GEMM_SMEM = (128 * LDA + 128 * LDB) * 2;   // 69632 B
    if (!s1) {
        cudaStreamCreateWithFlags(&s1, cudaStreamNonBlocking);
        cudaEventCreateWithFlags(&evFork, cudaEventDisableTiming);
        cudaEventCreateWithFlags(&evJoin, cudaEventDisableTiming);
    }
    if (!smem_set) {
        cudaFuncSetAttribute(gemm_kernel, cudaFuncAttributeMaxDynamicSharedMemorySize, GEMM_SMEM);
        smem_set = true;
    }

    // stream 1: proj -> edge attention (edge order), overlapped with CSR chain
    cudaEventRecord(evFork, 0);
    cudaStreamWaitEvent(s1, evFork, 0);
    proj_kernel<<<(NN + PROJ_NODES - 1) / PROJ_NODES, 256, 0, s1>>>(x, Wr, Wc);
    edge_atten_kernel<<<(EE / 2 + 255) / 256, 256, 0, s1>>>(row, col);
    cudaEventRecord(evJoin, s1);

    // stream 0: CSR construction
    hist_kernel<<<(EE / 4 + 255) / 256, 256>>>(row, Wx);
    scanA_kernel<<<NBLK, 1024>>>();
    scanBC_kernel<<<NBLK, 1024>>>();

    // join: scatter needs deg + ea from stream 1
    cudaStreamWaitEvent(0, evJoin, 0);
    scatter_kernel<<<(EE / 4 + 255) / 256, 256>>>(row, col, adj);
    spmm_kernel<<<(NN + 7) / 8, 256>>>();
    gemm_kernel<<<dim3(DOUT / 128, (NN + 127) / 128), 256, GEMM_SMEM>>>(bx, out);
}

// round 14
// speedup vs baseline: 1.6724x; 1.6724x over previous
#include <cuda_runtime.h>
#include <cuda_fp16.h>
#include <cuda_bf16.h>

#define NN   50000
#define EE   1600000
#define DIN  128
#define DOUT 256
#define DA   32
#define NBLK ((NN + 1023) / 1024)   // 49
#define CACHE 4                      // cached chunks per lane (deg <= 128)

typedef unsigned long long ull;

// ---------------- device scratch (static, no allocations) ----------------
__device__ __half2 g_arowh[NN * 16];        // a_row as half2 (3.2 MB)
__device__ __half2 g_acolh[NN * 16];        // a_col as half2 (3.2 MB)
__device__ __half2 g_xh[NN * 64];           // x as half2     (12.8 MB)
__device__ __half2 g_hh[NN * 64];           // h as half2     (12.8 MB)
__device__ __half  g_Wh[DIN * DOUT];        // W_x as half    (64 KB)
__device__ int    g_cnt [NN];               // zero-init; self-cleaned by scanA
__device__ int    g_cnt2[NN];               // zero-init; self-cleaned by fused
__device__ int    g_off [NN + 1];
__device__ int    g_bsum[NBLK];
__device__ uint2  g_ecol[EE];               // {col*32, adj fp32 bits} CSR order — 12.8 MB
__device__ float  g_ea[EE];                 // exp(atten) overflow store (c >= CACHE only)

// ---------------- kernel 1: projections + x->half2 convert ----------------
#define PROJ_NODES 16
__global__ __launch_bounds__(256) void proj_kernel(
    const float* __restrict__ x,
    const float* __restrict__ Wr,
    const float* __restrict__ Wc)
{
    __shared__ float Wsh[DIN][2 * DA];          // cols [0,32)=W_row, [32,64)=W_col
    __shared__ float xsh[PROJ_NODES][DIN + 1];
    int t = threadIdx.x;

    for (int i = t; i < DIN * DA; i += 256) {
        int k = i >> 5, j = i & 31;
        Wsh[k][j]      = Wr[i];
        Wsh[k][j + 32] = Wc[i];
    }
    int node0 = blockIdx.x * PROJ_NODES;
    for (int i = t; i < PROJ_NODES * DIN; i += 256) {
        int n = i >> 7, k = i & 127;
        int gn = node0 + n;
        xsh[n][k] = (gn < NN) ? x[gn * DIN + k] : 0.f;
    }
    __syncthreads();

    // write x as half2 (free conversion: x already staged in smem)
    for (int i = t; i < PROJ_NODES * 64; i += 256) {
        int n = i >> 6, k2 = i & 63;
        int gn = node0 + n;
        if (gn < NN)
            g_xh[gn * 64 + k2] = __floats2half2_rn(xsh[n][2 * k2], xsh[n][2 * k2 + 1]);
    }

    int n  = t & 15;       // local node
    int g  = t >> 4;       // output group 0..15 -> dims g*4..g*4+3
    int j0 = g * 4;
    float a0 = 0.f, a1 = 0.f, a2 = 0.f, a3 = 0.f;
#pragma unroll 8
    for (int k = 0; k < DIN; k++) {
        float xv = xsh[n][k];
        a0 += xv * Wsh[k][j0 + 0];
        a1 += xv * Wsh[k][j0 + 1];
        a2 += xv * Wsh[k][j0 + 2];
        a3 += xv * Wsh[k][j0 + 3];
    }
    int gn = node0 + n;
    if (gn < NN) {
        if (j0 < DA) {
            g_arowh[gn * 16 + (j0 >> 1)]     = __floats2half2_rn(a0, a1);
            g_arowh[gn * 16 + (j0 >> 1) + 1] = __floats2half2_rn(a2, a3);
        } else {
            int j = j0 - DA;
            g_acolh[gn * 16 + (j >> 1)]      = __floats2half2_rn(a0, a1);
            g_acolh[gn * 16 + (j >> 1) + 1]  = __floats2half2_rn(a2, a3);
        }
    }
}

// ---------------- kernel 2: degree histogram (4 edges/thread) + W convert ----------------
__global__ void hist_kernel(const int* __restrict__ row, const float* __restrict__ W) {
    int i = blockIdx.x * blockDim.x + threadIdx.x;
    if (i < DIN * DOUT) g_Wh[i] = __float2half(W[i]);
    int e4 = i * 4;
    if (e4 < EE) {
        int4 r = *(const int4*)&row[e4];
        atomicAdd(&g_cnt[r.x], 1);
        atomicAdd(&g_cnt[r.y], 1);
        atomicAdd(&g_cnt[r.z], 1);
        atomicAdd(&g_cnt[r.w], 1);
    }
}

// ---------------- kernel 3a: block scan (self-cleans g_cnt for next replay) ----------------
__global__ __launch_bounds__(1024) void scanA_kernel() {
    __shared__ int wsum[32];
    int b = blockIdx.x, t = threadIdx.x;
    int i = b * 1024 + t;
    int lane = t & 31, w = t >> 5;
    int v = (i < NN) ? g_cnt[i] : 0;
    if (i < NN) g_cnt[i] = 0;                 // self-clean for next graph replay
    int s = v;
#pragma unroll
    for (int d = 1; d < 32; d <<= 1) {
        int n = __shfl_up_sync(0xffffffffu, s, d);
        if (lane >= d) s += n;
    }
    if (lane == 31) wsum[w] = s;
    __syncthreads();
    if (w == 0) {
        int ws = wsum[lane];
#pragma unroll
        for (int d = 1; d < 32; d <<= 1) {
            int n = __shfl_up_sync(0xffffffffu, ws, d);
            if (lane >= d) ws += n;
        }
        wsum[lane] = ws;
    }
    __syncthreads();
    int incl = s + (w > 0 ? wsum[w - 1] : 0);
    if (i < NN) g_off[i + 1] = incl;          // block-local inclusive
    if (t == 1023) g_bsum[b] = incl;          // block total
}

// ---------------- kernel 3b: merged block-sum scan + offset add ----------------
__global__ __launch_bounds__(1024) void scanBC_kernel() {
    __shared__ int pre[64];
    int b = blockIdx.x, t = threadIdx.x;
    if (t < 64) pre[t] = (t < NBLK) ? g_bsum[t] : 0;
    __syncthreads();
#pragma unroll
    for (int s = 1; s < 64; s <<= 1) {
        int a = (t >= s && t < 64) ? pre[t - s] : 0;
        __syncthreads();
        if (t < 64) pre[t] += a;
        __syncthreads();
    }
    int add = (b > 0) ? pre[b - 1] : 0;
    int i = b * 1024 + t;
    if (i < NN) g_off[i + 1] += add;
    if (b == 0 && t == 0) g_off[0] = 0;
}

// ---------------- kernel 4: minimal CSR scatter of {col, adj} (4 edges/thread) ----------------
__global__ __launch_bounds__(256) void scatter_kernel(
    const int*   __restrict__ row,
    const int*   __restrict__ col,
    const float* __restrict__ adj)
{
    int i = blockIdx.x * blockDim.x + threadIdx.x;
    int e = i * 4;
    if (e >= EE) return;
    int4   r4 = *(const int4*)&row[e];
    int4   c4 = *(const int4*)&col[e];
    float4 a4 = *(const float4*)&adj[e];
    int p0 = g_off[r4.x] + atomicAdd(&g_cnt2[r4.x], 1);
    g_ecol[p0] = make_uint2((unsigned)(c4.x * 32), __float_as_uint(a4.x));
    int p1 = g_off[r4.y] + atomicAdd(&g_cnt2[r4.y], 1);
    g_ecol[p1] = make_uint2((unsigned)(c4.y * 32), __float_as_uint(a4.y));
    int p2 = g_off[r4.z] + atomicAdd(&g_cnt2[r4.z], 1);
    g_ecol[p2] = make_uint2((unsigned)(c4.z * 32), __float_as_uint(a4.z));
    int p3 = g_off[r4.w] + atomicAdd(&g_cnt2[r4.w], 1);
    g_ecol[p3] = make_uint2((unsigned)(c4.w * 32), __float_as_uint(a4.w));
}

// ---------------- kernel 5: fused attention + SpMM (two-pass, register-cached edges) ----------------
__global__ __launch_bounds__(256) void fused_kernel() {
    int w = threadIdx.x >> 5, lane = threadIdx.x & 31;
    int i = blockIdx.x * 8 + w;
    if (i >= NN) return;
    int start = g_off[i], end = g_off[i + 1];
    if (lane == 0) g_cnt2[i] = 0;              // self-clean for next graph replay

    __shared__ float2 stage[8][32];            // per-warp broadcast buffer

    // a_row[i]: 64 B, broadcast load into registers (all lanes same address)
    uint4 ar[4];
    const uint4* arp = (const uint4*)&g_arowh[i * 16];
#pragma unroll
    for (int q = 0; q < 4; q++) ar[q] = arp[q];

    // per-lane register cache of chunk data (covers deg <= 32*CACHE)
    float    ea_c [CACHE];
    unsigned col_c[CACHE];
    unsigned adj_c[CACHE];

    // ---- pass 1: per-edge attention, denominator in registers ----
    float degacc = 0.f;
    {
        int c = 0;
        for (int base = start; base < end; base += 32, c++) {
            int k = base + lane;
            float ea = 0.f;
            uint2 ca = make_uint2(0u, 0u);
            if (k < end) {
                ca = g_ecol[k];                            // {col*32, adj bits}
                const uint4* ac4 = (const uint4*)&g_acolh[(ca.x >> 5) * 16];
                float dot = 0.f;
#pragma unroll
                for (int q = 0; q < 4; q++) {
                    uint4 A = ar[q], B = __ldg(&ac4[q]);
                    const __half2* ah = (const __half2*)&A;
                    const __half2* bh = (const __half2*)&B;
#pragma unroll
                    for (int j = 0; j < 4; j++) {
                        float2 a = __half22float2(ah[j]);
                        float2 b = __half22float2(bh[j]);
                        dot += a.x * b.x + a.y * b.y;
                    }
                }
                float s = dot * 0.17677669529663687f;      // rsqrt(32)
                if (s < 0.f) s *= 0.2f;                    // leaky relu
                ea = __expf(s);
                degacc += ea;
            }
            if (c < CACHE) {
                ea_c[c] = ea; col_c[c] = ca.x; adj_c[c] = ca.y;
            } else if (k < end) {
                g_ea[k] = ea;                              // rare overflow path
            }
        }
    }
#pragma unroll
    for (int s = 16; s > 0; s >>= 1) degacc += __shfl_xor_sync(0xffffffffu, degacc, s);
    float inv = 1.f / (degacc + 1e-15f);

    // ---- pass 2: x gather accumulate (register-cached vals; full/tail split) ----
    const uint2* x2 = (const uint2*)g_xh;      // one uint2 = 4 dims; row = 32 uint2
    float a0 = 0.f, a1 = 0.f, a2 = 0.f, a3 = 0.f;
    int base = start, c = 0;
    for (; base + 32 <= end; base += 32, c++) {
        float myval; unsigned mycol;
        if (c < CACHE) {
            myval = (__uint_as_float(adj_c[c]) + ea_c[c] * inv) * 0.5f;
            mycol = col_c[c];
        } else {
            uint2 ca = g_ecol[base + lane];
            myval = (__uint_as_float(ca.y) + g_ea[base + lane] * inv) * 0.5f;
            mycol = ca.x;
        }
        stage[w][lane] = make_float2(myval, __uint_as_float(mycol));
        __syncwarp();
#pragma unroll 8
        for (int j = 0; j < 32; j++) {
            float2 vc = stage[w][j];                       // LDS.64 broadcast
            float v  = vc.x;
            int   cb = (int)__float_as_uint(vc.y);
            uint2 xv = __ldg(&x2[cb + lane]);
            __half2 xa = *reinterpret_cast<__half2*>(&xv.x);
            __half2 xb = *reinterpret_cast<__half2*>(&xv.y);
            float2 fa = __half22float2(xa);
            float2 fb = __half22float2(xb);
            a0 += v * fa.x; a1 += v * fa.y;
            a2 += v * fb.x; a3 += v * fb.y;
        }
        __syncwarp();
    }
    if (base < end) {
        int k = base + lane;
        float myval = 0.f;
        unsigned mycol = 0;
        if (k < end) {
            if (c < CACHE) {
                myval = (__uint_as_float(adj_c[c]) + ea_c[c] * inv) * 0.5f;
                mycol = col_c[c];
            } else {
                uint2 ca = g_ecol[k];
                myval = (__uint_as_float(ca.y) + g_ea[k] * inv) * 0.5f;
                mycol = ca.x;
            }
        }
        stage[w][lane] = make_float2(myval, __uint_as_float(mycol));
        __syncwarp();
        int m = end - base;
        for (int j = 0; j < m; j++) {
            float2 vc = stage[w][j];
            float v  = vc.x;
            int   cb = (int)__float_as_uint(vc.y);
            uint2 xv = __ldg(&x2[cb + lane]);
            __half2 xa = *reinterpret_cast<__half2*>(&xv.x);
            __half2 xb = *reinterpret_cast<__half2*>(&xv.y);
            float2 fa = __half22float2(xa);
            float2 fb = __half22float2(xb);
            a0 += v * fa.x; a1 += v * fa.y;
            a2 += v * fb.x; a3 += v * fb.y;
        }
    }

    uint2 o;
    __half2 o0 = __floats2half2_rn(a0, a1);
    __half2 o1 = __floats2half2_rn(a2, a3);
    o.x = *reinterpret_cast<unsigned*>(&o0);
    o.y = *reinterpret_cast<unsigned*>(&o1);
    *(uint2*)&g_hh[i * 64 + lane * 2] = o;
}

// ---------------- kernel 6: out = h @ W_x + b_x (HMMA m16n8k16) ----------------
// BM=128, BN=128, single K=128 pass. 256 threads (8 warps), warp tile 32x64.
#define LDA 136
#define LDB 136
__global__ __launch_bounds__(256) void gemm_kernel(
    const float* __restrict__ bias,
    float* __restrict__ out)
{
    extern __shared__ __half sm[];
    __half* As = sm;                 // [128][LDA]
    __half* Bs = sm + 128 * LDA;     // [128][LDB]

    int tid = threadIdx.x;
    int m0  = blockIdx.y * 128;
    int n0g = blockIdx.x * 128;

    // load A: h rows m0..m0+127 (256 B each = 16 uint4)
    const uint4* hsrc = (const uint4*)g_hh;
#pragma unroll
    for (int p = 0; p < 8; p++) {
        int idx = tid + 256 * p;
        int r = idx >> 4, seg = idx & 15;
        uint4 v = make_uint4(0u, 0u, 0u, 0u);
        if (m0 + r < NN) v = hsrc[(m0 + r) * 16 + seg];
        *(uint4*)&As[r * LDA + seg * 8] = v;
    }
    // load B: W rows k=0..127, cols n0g..n0g+127 (16 uint4 per row slice)
    const uint4* wsrc = (const uint4*)g_Wh;
#pragma unroll
    for (int p = 0; p < 8; p++) {
        int idx = tid + 256 * p;
        int kk = idx >> 4, seg = idx & 15;
        uint4 v = wsrc[kk * 32 + (n0g >> 3) + seg];
        *(uint4*)&Bs[kk * LDB + seg * 8] = v;
    }
    __syncthreads();

    int w    = tid >> 5;
    int lane = tid & 31;
    int wm = (w & 3) * 32;       // warp row offset
    int wn = (w >> 2) * 64;      // warp col offset

    float acc[2][8][4];
#pragma unroll
    for (int mt = 0; mt < 2; mt++)
#pragma unroll
        for (int nt = 0; nt < 8; nt++)
#pragma unroll
            for (int q = 0; q < 4; q++) acc[mt][nt][q] = 0.f;

#pragma unroll
    for (int ks = 0; ks < 8; ks++) {
        int k0 = ks * 16;
        unsigned afr[2][4];
#pragma unroll
        for (int mt = 0; mt < 2; mt++) {
            int r = wm + mt * 16 + (lane & 15);
            int c = k0 + (lane >> 4) * 8;
            unsigned addr = (unsigned)__cvta_generic_to_shared(&As[r * LDA + c]);
            asm volatile("ldmatrix.sync.aligned.m8n8.x4.shared.b16 {%0,%1,%2,%3}, [%4];"
                : "=r"(afr[mt][0]), "=r"(afr[mt][1]), "=r"(afr[mt][2]), "=r"(afr[mt][3])
                : "r"(addr));
        }
        unsigned bfr[8][2];
#pragma unroll
        for (int ntp = 0; ntp < 4; ntp++) {
            int kk = k0 + (lane & 15);
            int nn = wn + ntp * 16 + (lane >> 4) * 8;
            unsigned addr = (unsigned)__cvta_generic_to_shared(&Bs[kk * LDB + nn]);
            unsigned r0, r1, r2, r3;
            asm volatile("ldmatrix.sync.aligned.m8n8.x4.trans.shared.b16 {%0,%1,%2,%3}, [%4];"
                : "=r"(r0), "=r"(r1), "=r"(r2), "=r"(r3) : "r"(addr));
            bfr[ntp * 2][0] = r0;     bfr[ntp * 2][1] = r1;
            bfr[ntp * 2 + 1][0] = r2; bfr[ntp * 2 + 1][1] = r3;
        }
#pragma unroll
        for (int mt = 0; mt < 2; mt++)
#pragma unroll
            for (int nt = 0; nt < 8; nt++) {
                asm volatile(
                    "mma.sync.aligned.m16n8k16.row.col.f32.f16.f16.f32 "
                    "{%0,%1,%2,%3}, {%4,%5,%6,%7}, {%8,%9}, {%0,%1,%2,%3};"
                    : "+f"(acc[mt][nt][0]), "+f"(acc[mt][nt][1]),
                      "+f"(acc[mt][nt][2]), "+f"(acc[mt][nt][3])
                    : "r"(afr[mt][0]), "r"(afr[mt][1]), "r"(afr[mt][2]), "r"(afr[mt][3]),
                      "r"(bfr[nt][0]), "r"(bfr[nt][1]));
            }
    }

    // epilogue
    int g   = lane >> 2;
    int tig = lane & 3;
#pragma unroll
    for (int mt = 0; mt < 2; mt++) {
#pragma unroll
        for (int nt = 0; nt < 8; nt++) {
            int colg = n0g + wn + nt * 8 + tig * 2;
            float b0 = bias[colg], b1 = bias[colg + 1];
            int r0 = m0 + wm + mt * 16 + g;
            if (r0 < NN) {
                float2 v0 = make_float2(acc[mt][nt][0] + b0, acc[mt][nt][1] + b1);
                *(float2*)&out[r0 * DOUT + colg] = v0;
            }
            int r1 = r0 + 8;
            if (r1 < NN) {
                float2 v1 = make_float2(acc[mt][nt][2] + b0, acc[mt][nt][3] + b1);
                *(float2*)&out[r1 * DOUT + colg] = v1;
            }
        }
    }
}

// ---------------- launch ----------------
extern "C" void kernel_launch(void* const* d_in, const int* in_sizes, int n_in,
                              void* d_out, int out_size)
{
    const float* x    = (const float*)d_in[0];
    const int*   row  = (const int*)  d_in[1];
    const int*   col  = (const int*)  d_in[2];
    const float* adj  = (const float*)d_in[3];
    const float* Wr   = (const float*)d_in[4];
    const float* Wc   = (const float*)d_in[5];
    const float* Wx   = (const float*)d_in[6];
    const float* bx   = (const float*)d_in[7];
    float* out = (float*)d_out;

    // one-time resources (no device memory; identical captured work every call)
    static cudaStream_t s1 = nullptr;
    static cudaEvent_t evFork = nullptr, evJoin = nullptr;
    static bool smem_set = false;
    const int GEMM_SMEM = (128 * LDA + 128 * LDB) * 2;   // 69632 B
    if (!s1) {
        cudaStreamCreateWithFlags(&s1, cudaStreamNonBlocking);
        cudaEventCreateWithFlags(&evFork, cudaEventDisableTiming);
        cudaEventCreateWithFlags(&evJoin, cudaEventDisableTiming);
    }
    if (!smem_set) {
        cudaFuncSetAttribute(gemm_kernel, cudaFuncAttributeMaxDynamicSharedMemorySize, GEMM_SMEM);
        smem_set = true;
    }

    // fork: proj on s1 runs concurrently with hist+scan+scatter chain
    cudaEventRecord(evFork, 0);
    cudaStreamWaitEvent(s1, evFork, 0);
    proj_kernel<<<(NN + PROJ_NODES - 1) / PROJ_NODES, 256, 0, s1>>>(x, Wr, Wc);
    cudaEventRecord(evJoin, s1);

    hist_kernel<<<(EE / 4 + 255) / 256, 256>>>(row, Wx);
    scanA_kernel<<<NBLK, 1024>>>();
    scanBC_kernel<<<NBLK, 1024>>>();
    scatter_kernel<<<(EE / 4 + 255) / 256, 256>>>(row, col, adj);

    // join: fused attention+spmm needs proj outputs + CSR
    cudaStreamWaitEvent(0, evJoin, 0);
    fused_kernel<<<(NN + 7) / 8, 256>>>();
    gemm_kernel<<<dim3(DOUT / 128, (NN + 127) / 128), 256, GEMM_SMEM>>>(bx, out);
}